// round 1
// baseline (speedup 1.0000x reference)
#include <cuda_runtime.h>
#include <math.h>

// ---------------------------------------------------------------------------
// GaussCrossEntropyLoss: fused focal CE + per-cloud asymmetric gaussian weight
// Inputs (metadata order): pred f32 (N,2), coord f32 (N,3), segment i32 (N),
//                          offset i32 (B)  -- cumulative, offset[B-1]==N
// Output: f32 scalar (mean loss)
// ---------------------------------------------------------------------------

#define FULLMASK 0xFFFFFFFFu
#define MAXB 8

// Scratch state (re-initialized by k_init every graph replay)
__device__ float g_gmax[MAXB];   // max z over ground points  (-inf if none)
__device__ float g_pmin[MAXB];   // min z over plant points   (+inf if none)
__device__ float g_zmin[MAXB];   // min z overall
__device__ float g_zmax[MAXB];   // max z overall
__device__ float g_acc[32];      // partial loss sums

// float atomic max/min via ordered integer bit tricks (valid for mixed signs,
// no NaNs in this data). Works on both shared and global pointers.
__device__ __forceinline__ void atomicMaxF(float* a, float v) {
    if (v >= 0.0f) atomicMax((int*)a, __float_as_int(v));
    else           atomicMin((unsigned int*)a, __float_as_uint(v));
}
__device__ __forceinline__ void atomicMinF(float* a, float v) {
    if (v >= 0.0f) atomicMin((int*)a, __float_as_int(v));
    else           atomicMax((unsigned int*)a, __float_as_uint(v));
}

// searchsorted(offset, i, side='right') == count of offsets <= i
__device__ __forceinline__ int batch_of(int i, const int* s_off) {
    int b = 0;
#pragma unroll
    for (int k = 0; k < MAXB; k++) b += (i >= s_off[k]);
    return b;
}

__global__ void k_init() {
    int t = threadIdx.x;
    g_acc[t] = 0.0f;
    if (t < MAXB) {
        g_gmax[t] = -INFINITY;
        g_pmin[t] =  INFINITY;
        g_zmin[t] =  INFINITY;
        g_zmax[t] = -INFINITY;
    }
}

// ---------------------------------------------------------------------------
// Pass 1: per-cloud z statistics
// ---------------------------------------------------------------------------
__global__ void __launch_bounds__(256)
k_pass1(const float* __restrict__ coord, const int* __restrict__ segment,
        const int* __restrict__ offset, int n, int nb)
{
    __shared__ int   s_off[MAXB];
    __shared__ float s_gmax[MAXB], s_pmin[MAXB], s_zmin[MAXB], s_zmax[MAXB];
    const int tid = threadIdx.x;
    if (tid < MAXB) {
        s_off[tid]  = (tid < nb) ? offset[tid] : 0x7FFFFFFF;
        s_gmax[tid] = -INFINITY;  s_pmin[tid] = INFINITY;
        s_zmin[tid] =  INFINITY;  s_zmax[tid] = -INFINITY;
    }
    __syncthreads();

    const int t    = blockIdx.x * blockDim.x + tid;
    const int base = t * 4;
    const bool fullv = (base + 3 < n);

    float z[4];
    int   sg[4];
    int   b0 = 0;
    bool  uni = false;

    if (fullv) {
        const float4* c4 = (const float4*)coord;
        float4 ca = c4[3 * t + 0];
        float4 cb = c4[3 * t + 1];
        float4 cc = c4[3 * t + 2];
        z[0] = ca.z; z[1] = cb.y; z[2] = cc.x; z[3] = cc.w;
        int4 s4 = ((const int4*)segment)[t];
        sg[0] = s4.x; sg[1] = s4.y; sg[2] = s4.z; sg[3] = s4.w;
        b0 = batch_of(base, s_off);
        uni = (b0 == batch_of(base + 3, s_off));   // batch ids monotonic
    }

    const int  wb   = __shfl_sync(FULLMASK, b0, 0);
    const bool wuni = __all_sync(FULLMASK, fullv && uni && (b0 == wb));

    if (wuni) {
        // fast path: whole warp is one cloud — register + shuffle reduction
        float lg = -INFINITY, lp = INFINITY, lmn = INFINITY, lmx = -INFINITY;
#pragma unroll
        for (int j = 0; j < 4; j++) {
            float zz = z[j];
            if (sg[j] == 0) lg = fmaxf(lg, zz); else lp = fminf(lp, zz);
            lmn = fminf(lmn, zz);
            lmx = fmaxf(lmx, zz);
        }
#pragma unroll
        for (int o = 16; o > 0; o >>= 1) {
            lg  = fmaxf(lg,  __shfl_xor_sync(FULLMASK, lg,  o));
            lp  = fminf(lp,  __shfl_xor_sync(FULLMASK, lp,  o));
            lmn = fminf(lmn, __shfl_xor_sync(FULLMASK, lmn, o));
            lmx = fmaxf(lmx, __shfl_xor_sync(FULLMASK, lmx, o));
        }
        if ((tid & 31) == 0) {
            if (lg > -INFINITY) atomicMaxF(&s_gmax[wb], lg);
            if (lp <  INFINITY) atomicMinF(&s_pmin[wb], lp);
            atomicMinF(&s_zmin[wb], lmn);
            atomicMaxF(&s_zmax[wb], lmx);
        }
    } else {
        // slow path: boundary / tail lanes — per-point smem atomics
#pragma unroll
        for (int j = 0; j < 4; j++) {
            int i = base + j;
            if (i < n) {
                float zz = fullv ? z[j]  : coord[3 * i + 2];
                int   ss = fullv ? sg[j] : segment[i];
                int   b  = batch_of(i, s_off);
                if (ss == 0) atomicMaxF(&s_gmax[b], zz);
                else         atomicMinF(&s_pmin[b], zz);
                atomicMinF(&s_zmin[b], zz);
                atomicMaxF(&s_zmax[b], zz);
            }
        }
    }
    __syncthreads();

    // block -> global: only non-identity values escape (<=4 REDs typical)
    if (tid < 32) {
        int b = tid >> 2, k = tid & 3;
        if (k == 0) { float v = s_gmax[b]; if (v > -INFINITY) atomicMaxF(&g_gmax[b], v); }
        else if (k == 1) { float v = s_pmin[b]; if (v <  INFINITY) atomicMinF(&g_pmin[b], v); }
        else if (k == 2) { float v = s_zmin[b]; if (v <  INFINITY) atomicMinF(&g_zmin[b], v); }
        else             { float v = s_zmax[b]; if (v > -INFINITY) atomicMaxF(&g_zmax[b], v); }
    }
}

// ---------------------------------------------------------------------------
// Pass 2: focal CE * gaussian weight, summed
// ---------------------------------------------------------------------------
__device__ __forceinline__ float point_loss(float x0, float x1, int s,
                                            float zz, float mu)
{
    // log_softmax over 2 classes
    float m   = fmaxf(x0, x1);
    float mn  = fminf(x0, x1);
    float lse = m + log1pf(__expf(mn - m));
    float lt  = (s ? x1 : x0) - lse;      // log p_t
    float pt  = __expf(lt);
    float om  = 1.0f - pt;
    float fw  = om * om;                  // focal (alpha=1, gamma=2)
    // asymmetric gaussian weight
    float d = zz - mu;
    float w;
    if (zz <= mu) w = __expf(-50.0f * d * d);                      // 1/(2*0.1^2)
    else          w = (d > 0.8f) ? 0.1f : __expf(-3.125f * d * d); // 1/(2*0.4^2)
    return (-lt) * fw * w;
}

__global__ void __launch_bounds__(256)
k_pass2(const float* __restrict__ pred, const float* __restrict__ coord,
        const int* __restrict__ segment, const int* __restrict__ offset,
        int n, int nb)
{
    __shared__ int   s_off[MAXB];
    __shared__ float s_mu[MAXB];
    __shared__ float s_part[8];
    const int tid = threadIdx.x;
    if (tid < MAXB) {
        s_off[tid] = (tid < nb) ? offset[tid] : 0x7FFFFFFF;
        float g = g_gmax[tid]; if (isinf(g)) g = g_zmin[tid];
        float p = g_pmin[tid]; if (isinf(p)) p = g_zmax[tid];
        s_mu[tid] = g + (p - g) * 0.5f;   // exact reference expression
    }
    __syncthreads();

    const int t    = blockIdx.x * blockDim.x + tid;
    const int base = t * 4;
    float acc = 0.0f;

    if (base + 3 < n) {
        const float4* p4 = (const float4*)pred;
        float4 pa = p4[2 * t + 0];
        float4 pb = p4[2 * t + 1];
        const float4* c4 = (const float4*)coord;
        float4 ca = c4[3 * t + 0];
        float4 cb = c4[3 * t + 1];
        float4 cc = c4[3 * t + 2];
        int4 s4 = ((const int4*)segment)[t];

        float z[4]  = { ca.z, cb.y, cc.x, cc.w };
        float x0[4] = { pa.x, pa.z, pb.x, pb.z };
        float x1[4] = { pa.y, pa.w, pb.y, pb.w };
        int   sg[4] = { s4.x, s4.y, s4.z, s4.w };
#pragma unroll
        for (int j = 0; j < 4; j++) {
            int b = batch_of(base + j, s_off);
            acc += point_loss(x0[j], x1[j], sg[j], z[j], s_mu[b]);
        }
    } else {
#pragma unroll
        for (int j = 0; j < 4; j++) {
            int i = base + j;
            if (i < n) {
                int b = batch_of(i, s_off);
                acc += point_loss(pred[2 * i], pred[2 * i + 1], segment[i],
                                  coord[3 * i + 2], s_mu[b]);
            }
        }
    }

#pragma unroll
    for (int o = 16; o > 0; o >>= 1)
        acc += __shfl_xor_sync(FULLMASK, acc, o);
    if ((tid & 31) == 0) s_part[tid >> 5] = acc;
    __syncthreads();
    if (tid == 0) {
        float s = 0.0f;
#pragma unroll
        for (int k = 0; k < 8; k++) s += s_part[k];
        atomicAdd(&g_acc[blockIdx.x & 31], s);
    }
}

__global__ void k_final(float* out, float inv_n) {
    int t = threadIdx.x;
    float v = g_acc[t];
#pragma unroll
    for (int o = 16; o > 0; o >>= 1)
        v += __shfl_xor_sync(FULLMASK, v, o);
    if (t == 0) out[0] = v * inv_n;
}

// ---------------------------------------------------------------------------
extern "C" void kernel_launch(void* const* d_in, const int* in_sizes, int n_in,
                              void* d_out, int out_size)
{
    const float* pred    = (const float*)d_in[0];
    const float* coord   = (const float*)d_in[1];
    const int*   segment = (const int*)d_in[2];
    const int*   offset  = (const int*)d_in[3];
    int n  = in_sizes[2];
    int nb = in_sizes[3]; if (nb > MAXB) nb = MAXB;

    const int threads = 256;
    const int ppb     = threads * 4;
    const int blocks  = (n + ppb - 1) / ppb;

    k_init<<<1, 32>>>();
    k_pass1<<<blocks, threads>>>(coord, segment, offset, n, nb);
    k_pass2<<<blocks, threads>>>(pred, coord, segment, offset, n, nb);
    k_final<<<1, 32>>>((float*)d_out, 1.0f / (float)n);
}